// round 5
// baseline (speedup 1.0000x reference)
#include <cuda_runtime.h>
#include <cstdint>

#define CIN   256
#define CMID  512
#define COUT  256
#define IMGW  56
#define HW    3136
#define BATCH 32
#define KCONV 2304

// Scratch (device globals — allocation-free rule)
__device__ __align__(16) float g_x [BATCH * CIN  * HW];
__device__ __align__(16) float g_y [BATCH * CMID * HW + 8192];
__device__ __align__(16) float g_wA[CMID * KCONV];   // [m][k'] permuted
__device__ __align__(16) float g_wB[COUT * CMID];    // [m][k'] permuted, tf32

__device__ __forceinline__ uint32_t f2tf32(float f) {
    uint32_t r;
    asm("cvt.rna.tf32.f32 %0, %1;" : "=r"(r) : "f"(f));
    return r;
}
__device__ __forceinline__ void cp16(uint32_t dst, const float* src) {
    asm volatile("cp.async.cg.shared.global [%0], [%1], 16;\n" :: "r"(dst), "l"(src));
}

// ---------------- prep kernels ----------------
// g_wA[m][q] where q = kt*32 + k', k' = (kin%4)*8 + kin/4, k = kt*32 + kin
__global__ void prep_wA(const float* __restrict__ bw) {
    int idx = blockIdx.x * blockDim.x + threadIdx.x;
    if (idx >= CMID * KCONV) return;
    int q  = idx % KCONV;
    int m  = idx / KCONV;
    int kt = q >> 5;
    int kp = q & 31;
    int kin = ((kp & 7) << 2) + (kp >> 3);
    int k   = kt * 32 + kin;
    int ci = k & 255;
    int r  = k >> 8;
    int kh = r / 3, kw = r % 3;
    g_wA[idx] = bw[((m * CIN + ci) * 3 + kh) * 3 + kw];
}

__global__ void prep_wB(const float* __restrict__ fw) {
    int idx = blockIdx.x * blockDim.x + threadIdx.x;
    if (idx >= COUT * CMID) return;
    int q  = idx % CMID;
    int m  = idx / CMID;
    int kt = q >> 5;
    int kp = q & 31;
    int kin = ((kp & 7) << 2) + (kp >> 3);
    g_wB[idx] = __uint_as_float(f2tf32(fw[m * CMID + kt * 32 + kin]));
}

__global__ void prep_x(const float* __restrict__ x) {
    int idx = blockIdx.x * blockDim.x + threadIdx.x;
    if (idx >= BATCH * CIN * HW) return;
    g_x[idx] = __uint_as_float(f2tf32(x[idx]));
}

// ---------------- unified GEMM ----------------
// Block 256x128, BK=32, 8 warps (4M x 2N), warp tile 64x64.
// Smem: As[256][36], Bs[128][36] per stage, double buffered.
// A: cp.async from [m][k'] weights. B: reg-staged LDG + permuted STS.128.
#define BK 32
#define ASTRIDE 36
#define STAGEF ((256 + 128) * ASTRIDE)   // 13824 floats per stage

template <bool CONV1>
__global__ __launch_bounds__(256, 1)
void gemm_kernel(const float* __restrict__ bias, float* __restrict__ outp)
{
    constexpr int Ktot = CONV1 ? KCONV : CMID;
    constexpr int KT   = Ktot / BK;

    extern __shared__ float smem[];

    const int b    = blockIdx.z;
    const int m0   = blockIdx.y * 256;
    const int n0   = blockIdx.x * 128;
    const int tid  = threadIdx.x;
    const int lane = tid & 31;
    const int warp = tid >> 5;
    const int wm   = (warp & 3) * 64;
    const int wn   = (warp >> 2) * 64;

    const float* Aglob = (CONV1 ? g_wA : g_wB) + (size_t)m0 * Ktot;
    const float* Bbase = CONV1 ? (g_x + (size_t)b * CIN * HW)
                               : (g_y + (size_t)b * CMID * HW);

    // A loader coords: 4 rows x 8 chunks per warp-iteration
    const int ar0 = tid >> 3;          // 0..31
    const int ac  = tid & 7;           // chunk 0..7

    // B loader coords
    const int nl  = tid & 127;
    const int kr  = tid >> 7;          // 0..1
    const int n   = n0 + nl;
    const int hh  = n / IMGW;
    const int ww  = n % IMGW;

    float stage[16];

    float acc[4][8][4];
    #pragma unroll
    for (int i = 0; i < 4; i++)
        #pragma unroll
        for (int j = 0; j < 8; j++)
            #pragma unroll
            for (int c = 0; c < 4; c++) acc[i][j][c] = 0.f;

    auto load_A = [&](int kt, float* As) {
        uint32_t dbase = (uint32_t)__cvta_generic_to_shared(As);
        #pragma unroll
        for (int i = 0; i < 8; ++i) {
            int row = ar0 + 32 * i;
            cp16(dbase + (uint32_t)(row * ASTRIDE + ac * 4) * 4,
                 Aglob + (size_t)row * Ktot + kt * 32 + ac * 4);
        }
    };

    auto ldg_B = [&](int kt) {
        if (CONV1) {
            const int r   = kt >> 3;
            const int kh  = r / 3, kw = r % 3;
            const int ci0 = (kt & 7) * 32;
            const int ih  = hh + kh - 1;
            const int iw  = ww + kw - 1;
            const bool inb = ((unsigned)ih < (unsigned)IMGW) &&
                             ((unsigned)iw < (unsigned)IMGW);
            const float* src = Bbase + (size_t)(ci0 + kr) * HW + ih * IMGW + iw;
            #pragma unroll
            for (int j = 0; j < 16; ++j)
                stage[j] = inb ? __ldg(src + 2 * j * HW) : 0.f;
        } else {
            const float* src = Bbase + (size_t)(kt * 32 + kr) * HW + n;
            #pragma unroll
            for (int j = 0; j < 16; ++j)
                stage[j] = __ldg(src + 2 * j * HW);
        }
    };

    // Permuted STS: thread (kr) covers k = kr+2j -> k' groups
    auto sts_B = [&](float* Bs) {
        float* row = Bs + nl * ASTRIDE + kr * 8;
        float4 v;
        v = make_float4(stage[0], stage[2], stage[4],  stage[6]);
        *(float4*)(row +  0) = v;
        v = make_float4(stage[8], stage[10], stage[12], stage[14]);
        *(float4*)(row +  4) = v;
        v = make_float4(stage[1], stage[3], stage[5],  stage[7]);
        *(float4*)(row + 16) = v;
        v = make_float4(stage[9], stage[11], stage[13], stage[15]);
        *(float4*)(row + 20) = v;
    };

    const int gr = lane >> 2;
    const int kb = lane & 3;

    auto compute = [&](const float* As, const float* Bs) {
        #pragma unroll
        for (int half = 0; half < 2; ++half) {
            const int koff = kb * 8 + half * 4;
            float4 Bf[8];
            #pragma unroll
            for (int nt = 0; nt < 8; ++nt)
                Bf[nt] = *(const float4*)&Bs[(wn + nt * 8 + gr) * ASTRIDE + koff];
            #pragma unroll
            for (int mt = 0; mt < 4; ++mt) {
                const int row = wm + mt * 16 + gr;
                float4 A0 = *(const float4*)&As[row * ASTRIDE + koff];
                float4 A1 = *(const float4*)&As[(row + 8) * ASTRIDE + koff];
                const float a0k0 = A0.x, a1k0 = A1.x, a2k0 = A0.y, a3k0 = A1.y;
                const float a0k1 = A0.z, a1k1 = A1.z, a2k1 = A0.w, a3k1 = A1.w;
                #pragma unroll
                for (int nt = 0; nt < 8; ++nt) {
                    asm volatile(
                        "mma.sync.aligned.m16n8k8.row.col.f32.tf32.tf32.f32 "
                        "{%0,%1,%2,%3}, {%4,%5,%6,%7}, {%8,%9}, {%0,%1,%2,%3};\n"
                        : "+f"(acc[mt][nt][0]), "+f"(acc[mt][nt][1]),
                          "+f"(acc[mt][nt][2]), "+f"(acc[mt][nt][3])
                        : "r"(__float_as_uint(a0k0)), "r"(__float_as_uint(a1k0)),
                          "r"(__float_as_uint(a2k0)), "r"(__float_as_uint(a3k0)),
                          "r"(__float_as_uint(Bf[nt].x)), "r"(__float_as_uint(Bf[nt].y)));
                    asm volatile(
                        "mma.sync.aligned.m16n8k8.row.col.f32.tf32.tf32.f32 "
                        "{%0,%1,%2,%3}, {%4,%5,%6,%7}, {%8,%9}, {%0,%1,%2,%3};\n"
                        : "+f"(acc[mt][nt][0]), "+f"(acc[mt][nt][1]),
                          "+f"(acc[mt][nt][2]), "+f"(acc[mt][nt][3])
                        : "r"(__float_as_uint(a0k1)), "r"(__float_as_uint(a1k1)),
                          "r"(__float_as_uint(a2k1)), "r"(__float_as_uint(a3k1)),
                          "r"(__float_as_uint(Bf[nt].z)), "r"(__float_as_uint(Bf[nt].w)));
                }
            }
        }
    };

    // ---- pipelined main loop ----
    int buf = 0;
    load_A(0, smem);
    ldg_B(0);
    asm volatile("cp.async.commit_group;\n");

    for (int kt = 0; kt < KT; ++kt) {
        float* As = smem + buf * STAGEF;
        float* Bs = As + 256 * ASTRIDE;
        asm volatile("cp.async.wait_group 0;\n");
        sts_B(Bs);
        __syncthreads();
        if (kt + 1 < KT) {
            float* As1 = smem + (buf ^ 1) * STAGEF;
            load_A(kt + 1, As1);
            ldg_B(kt + 1);
            asm volatile("cp.async.commit_group;\n");
        }
        compute(As, Bs);
        buf ^= 1;
    }

    // ---- epilogue (float2 stores) ----
    float* dst = CONV1 ? (g_y + (size_t)b * CMID * HW)
                       : (outp + (size_t)b * COUT * HW);
    const int gc = (lane & 3) * 2;
    #pragma unroll
    for (int mt = 0; mt < 4; ++mt) {
        #pragma unroll
        for (int nt = 0; nt < 8; ++nt) {
            const int row = m0 + wm + mt * 16 + gr;
            const int col = n0 + wn + nt * 8 + gc;
            if (col < HW) {
                float2 v0, v1;
                if (CONV1) {
                    v0.x = __uint_as_float(f2tf32(fmaxf(acc[mt][nt][0], 0.f)));
                    v0.y = __uint_as_float(f2tf32(fmaxf(acc[mt][nt][1], 0.f)));
                    v1.x = __uint_as_float(f2tf32(fmaxf(acc[mt][nt][2], 0.f)));
                    v1.y = __uint_as_float(f2tf32(fmaxf(acc[mt][nt][3], 0.f)));
                } else {
                    float b0 = bias[row], b1 = bias[row + 8];
                    v0.x = acc[mt][nt][0] + b0;
                    v0.y = acc[mt][nt][1] + b0;
                    v1.x = acc[mt][nt][2] + b1;
                    v1.y = acc[mt][nt][3] + b1;
                }
                *(float2*)&dst[(size_t)row * HW + col]       = v0;
                *(float2*)&dst[(size_t)(row + 8) * HW + col] = v1;
            }
        }
    }
}

extern "C" void kernel_launch(void* const* d_in, const int* in_sizes, int n_in,
                              void* d_out, int out_size) {
    (void)in_sizes; (void)n_in; (void)out_size;
    const float* x  = (const float*)d_in[0];
    const float* bw = (const float*)d_in[1];
    const float* fw = (const float*)d_in[2];
    const float* fb = (const float*)d_in[3];
    float* out = (float*)d_out;

    const int smem_bytes = 2 * STAGEF * 4;   // 110592
    cudaFuncSetAttribute(gemm_kernel<true>,
                         cudaFuncAttributeMaxDynamicSharedMemorySize, smem_bytes);
    cudaFuncSetAttribute(gemm_kernel<false>,
                         cudaFuncAttributeMaxDynamicSharedMemorySize, smem_bytes);

    prep_wA<<<(CMID * KCONV + 255) / 256, 256>>>(bw);
    prep_wB<<<(COUT * CMID + 255) / 256, 256>>>(fw);
    prep_x <<<(BATCH * CIN * HW + 255) / 256, 256>>>(x);

    // conv1 + relu -> g_y : M=512 (2 tiles of 256), N=3136 (25 tiles of 128)
    gemm_kernel<true ><<<dim3(25, 2, 32), 256, smem_bytes>>>(nullptr, nullptr);
    // 1x1 conv + bias -> out : M=256 (1 tile)
    gemm_kernel<false><<<dim3(25, 1, 32), 256, smem_bytes>>>(fb, out);
}